// round 2
// baseline (speedup 1.0000x reference)
#include <cuda_runtime.h>

#define B_  2
#define S_  2048
#define H_  2048
#define NH_ 16
#define HD_ 128
#define M_  (B_ * S_)   // 4096 rows

// ---------------------------------------------------------------------------
// Scratch (allocation-free rule: __device__ globals)
// ---------------------------------------------------------------------------
__device__ float g_Q[(size_t)M_ * H_];
__device__ float g_K[(size_t)M_ * H_];
__device__ float g_V[(size_t)M_ * H_];
__device__ float g_O[(size_t)M_ * H_];

// ---------------------------------------------------------------------------
// GEMM: C[M,N] = A[M,K] @ W[N,K]^T + bias[N]
// A row-major [M,K], W row-major [N,K] (both K-contiguous), 128x128x16 tiles,
// 256 threads, 8x8 register tile per thread.
// ---------------------------------------------------------------------------
__global__ void __launch_bounds__(256)
gemm_bias_kernel(const float* __restrict__ A, const float* __restrict__ W,
                 const float* __restrict__ bias, float* __restrict__ C,
                 int M, int N, int K)
{
    __shared__ float As[16][128];
    __shared__ float Bs[16][128];

    const int tid = threadIdx.x;
    const int tx  = tid & 15;
    const int ty  = tid >> 4;
    const int m0  = blockIdx.y * 128;
    const int n0  = blockIdx.x * 128;

    float acc[8][8];
#pragma unroll
    for (int i = 0; i < 8; i++)
#pragma unroll
        for (int j = 0; j < 8; j++) acc[i][j] = 0.f;

    for (int kb = 0; kb < K; kb += 16) {
        // Load A/B tiles (128 rows x 16 k), transposed into smem [k][row].
#pragma unroll
        for (int l = 0; l < 2; l++) {
            int idx = tid + l * 256;      // 0..511
            int r   = idx >> 2;           // 0..127
            int kq  = (idx & 3) * 4;      // 0,4,8,12
            float4 va = *(const float4*)&A[(size_t)(m0 + r) * K + kb + kq];
            As[kq + 0][r] = va.x; As[kq + 1][r] = va.y;
            As[kq + 2][r] = va.z; As[kq + 3][r] = va.w;
            float4 vb = *(const float4*)&W[(size_t)(n0 + r) * K + kb + kq];
            Bs[kq + 0][r] = vb.x; Bs[kq + 1][r] = vb.y;
            Bs[kq + 2][r] = vb.z; Bs[kq + 3][r] = vb.w;
        }
        __syncthreads();

#pragma unroll
        for (int k = 0; k < 16; k++) {
            float4 a0 = *(const float4*)&As[k][ty * 8];
            float4 a1 = *(const float4*)&As[k][ty * 8 + 4];
            float4 b0 = *(const float4*)&Bs[k][tx * 8];
            float4 b1 = *(const float4*)&Bs[k][tx * 8 + 4];
            float ar[8] = {a0.x, a0.y, a0.z, a0.w, a1.x, a1.y, a1.z, a1.w};
            float br[8] = {b0.x, b0.y, b0.z, b0.w, b1.x, b1.y, b1.z, b1.w};
#pragma unroll
            for (int i = 0; i < 8; i++)
#pragma unroll
                for (int j = 0; j < 8; j++)
                    acc[i][j] = fmaf(ar[i], br[j], acc[i][j]);
        }
        __syncthreads();
    }

    // Epilogue: +bias, float4 stores
#pragma unroll
    for (int i = 0; i < 8; i++) {
        int m = m0 + ty * 8 + i;
#pragma unroll
        for (int j = 0; j < 8; j += 4) {
            int n = n0 + tx * 8 + j;
            float4 o;
            o.x = acc[i][j + 0] + bias[n + 0];
            o.y = acc[i][j + 1] + bias[n + 1];
            o.z = acc[i][j + 2] + bias[n + 2];
            o.w = acc[i][j + 3] + bias[n + 3];
            *(float4*)&C[(size_t)m * N + n] = o;
        }
    }
}

// ---------------------------------------------------------------------------
// Flash-style attention: per (batch,head), BQ=64 query rows per block,
// iterate KV in 64-row tiles with online softmax. 256 threads.
// Thread (tx 0..15, ty 0..15): owns rows ty*4+{0..3};
//   score cols tx+16*{0..3} (interleaved -> conflict-free K reads);
//   output cols tx*8+{0..7}.
// ---------------------------------------------------------------------------
#define BQ     64
#define BKT    64
#define KS_STR 129
#define PS_STR 66
// smem floats: Qs 64*128 + Ks 64*129 + Vs 64*128 + Ps 64*66
#define ATTN_SMEM_FLOATS (8192 + 8256 + 8192 + 4224)

__global__ void __launch_bounds__(256, 2)
attn_kernel(const float* __restrict__ Q, const float* __restrict__ K,
            const float* __restrict__ V, float* __restrict__ O)
{
    extern __shared__ float sm[];
    float* Qs = sm;             // [64][128]
    float* Ks = Qs + 8192;      // [64][129]
    float* Vs = Ks + 8256;      // [64][128]
    float* Ps = Vs + 8192;      // [64][66]

    const int tid = threadIdx.x;
    const int tx  = tid & 15;
    const int ty  = tid >> 4;
    const int bh  = blockIdx.y;
    const int b   = bh >> 4;
    const int h   = bh & 15;
    const int q0  = blockIdx.x * BQ;

    const size_t off = (size_t)b * S_ * H_ + (size_t)h * HD_;
    const float* Qg = Q + off;
    const float* Kg = K + off;
    const float* Vg = V + off;
    float*       Og = O + off;

    const float scale = 0.08838834764831845f;  // 1/sqrt(128)

    // Load + pre-scale Q tile
#pragma unroll
    for (int l = 0; l < 8; l++) {
        int idx = tid + l * 256;         // 0..2047
        int r   = idx >> 5;              // 0..63
        int c4  = (idx & 31);            // 0..31 (float4 index)
        float4 v = *(const float4*)&Qg[(size_t)(q0 + r) * H_ + c4 * 4];
        v.x *= scale; v.y *= scale; v.z *= scale; v.w *= scale;
        *(float4*)&Qs[r * 128 + c4 * 4] = v;
    }

    float m_i[4], l_i[4], acc[4][8];
#pragma unroll
    for (int i = 0; i < 4; i++) {
        m_i[i] = -1e30f; l_i[i] = 0.f;
#pragma unroll
        for (int j = 0; j < 8; j++) acc[i][j] = 0.f;
    }

    for (int kt = 0; kt < S_; kt += BKT) {
        __syncthreads();  // protect Ks/Vs/Ps from previous iteration consumers

        // Load K (scalar stores, padded stride) and V (float4) tiles
#pragma unroll
        for (int l = 0; l < 8; l++) {
            int idx = tid + l * 256;
            int r   = idx >> 5;
            int c   = (idx & 31) * 4;
            float4 kv = *(const float4*)&Kg[(size_t)(kt + r) * H_ + c];
            Ks[r * KS_STR + c + 0] = kv.x; Ks[r * KS_STR + c + 1] = kv.y;
            Ks[r * KS_STR + c + 2] = kv.z; Ks[r * KS_STR + c + 3] = kv.w;
            float4 vv = *(const float4*)&Vg[(size_t)(kt + r) * H_ + c];
            *(float4*)&Vs[r * 128 + c] = vv;
        }
        __syncthreads();

        // S = (Q*scale) @ K^T  : 4x4 per thread, cols interleaved tx+16j
        float s[4][4];
#pragma unroll
        for (int i = 0; i < 4; i++)
#pragma unroll
            for (int j = 0; j < 4; j++) s[i][j] = 0.f;

        const float4* Qs4 = (const float4*)Qs;
#pragma unroll 2
        for (int d4 = 0; d4 < 32; d4++) {
            float4 a4[4];
#pragma unroll
            for (int i = 0; i < 4; i++) a4[i] = Qs4[(ty * 4 + i) * 32 + d4];
#pragma unroll
            for (int dd = 0; dd < 4; dd++) {
                float b_[4];
#pragma unroll
                for (int j = 0; j < 4; j++)
                    b_[j] = Ks[(tx + 16 * j) * KS_STR + d4 * 4 + dd];
#pragma unroll
                for (int i = 0; i < 4; i++) {
                    float av = ((const float*)&a4[i])[dd];
#pragma unroll
                    for (int j = 0; j < 4; j++)
                        s[i][j] = fmaf(av, b_[j], s[i][j]);
                }
            }
        }

        // Online softmax. Lanes with same ty are a 16-lane half-warp (xor 1,2,4,8).
#pragma unroll
        for (int i = 0; i < 4; i++) {
            float mx = fmaxf(fmaxf(s[i][0], s[i][1]), fmaxf(s[i][2], s[i][3]));
#pragma unroll
            for (int o = 8; o > 0; o >>= 1)
                mx = fmaxf(mx, __shfl_xor_sync(0xffffffffu, mx, o));
            float mn    = fmaxf(m_i[i], mx);
            float alpha = __expf(m_i[i] - mn);
            m_i[i] = mn;
            float ls = 0.f;
#pragma unroll
            for (int j = 0; j < 4; j++) {
                float p = __expf(s[i][j] - mn);
                s[i][j] = p;
                ls += p;
            }
#pragma unroll
            for (int o = 8; o > 0; o >>= 1)
                ls += __shfl_xor_sync(0xffffffffu, ls, o);
            l_i[i] = l_i[i] * alpha + ls;
#pragma unroll
            for (int j = 0; j < 8; j++) acc[i][j] *= alpha;
#pragma unroll
            for (int j = 0; j < 4; j++)
                Ps[(ty * 4 + i) * PS_STR + tx + 16 * j] = s[i][j];
        }
        __syncthreads();

        // O += P @ V : 4 rows x 8 cols per thread
        const float4* Vs4 = (const float4*)Vs;
#pragma unroll 4
        for (int kk = 0; kk < BKT; kk++) {
            float4 v0 = Vs4[kk * 32 + tx * 2];
            float4 v1 = Vs4[kk * 32 + tx * 2 + 1];
#pragma unroll
            for (int i = 0; i < 4; i++) {
                float p = Ps[(ty * 4 + i) * PS_STR + kk];
                acc[i][0] = fmaf(p, v0.x, acc[i][0]);
                acc[i][1] = fmaf(p, v0.y, acc[i][1]);
                acc[i][2] = fmaf(p, v0.z, acc[i][2]);
                acc[i][3] = fmaf(p, v0.w, acc[i][3]);
                acc[i][4] = fmaf(p, v1.x, acc[i][4]);
                acc[i][5] = fmaf(p, v1.y, acc[i][5]);
                acc[i][6] = fmaf(p, v1.z, acc[i][6]);
                acc[i][7] = fmaf(p, v1.w, acc[i][7]);
            }
        }
    }

    // Finalize: divide by softmax denominator, write O tile
#pragma unroll
    for (int i = 0; i < 4; i++) {
        float inv = 1.f / l_i[i];
        int r = q0 + ty * 4 + i;
        float4 o0, o1;
        o0.x = acc[i][0] * inv; o0.y = acc[i][1] * inv;
        o0.z = acc[i][2] * inv; o0.w = acc[i][3] * inv;
        o1.x = acc[i][4] * inv; o1.y = acc[i][5] * inv;
        o1.z = acc[i][6] * inv; o1.w = acc[i][7] * inv;
        *(float4*)&Og[(size_t)r * H_ + tx * 8]     = o0;
        *(float4*)&Og[(size_t)r * H_ + tx * 8 + 4] = o1;
    }
}

// ---------------------------------------------------------------------------
// kernel_launch: 3 QKV GEMMs -> attention -> output GEMM. All graph-capturable.
// ---------------------------------------------------------------------------
extern "C" void kernel_launch(void* const* d_in, const int* in_sizes, int n_in,
                              void* d_out, int out_size)
{
    const float* X  = (const float*)d_in[0];
    const float* Wq = (const float*)d_in[1];
    const float* bq = (const float*)d_in[2];
    const float* Wk = (const float*)d_in[3];
    const float* bk = (const float*)d_in[4];
    const float* Wv = (const float*)d_in[5];
    const float* bv = (const float*)d_in[6];
    const float* Wo = (const float*)d_in[7];
    const float* bo = (const float*)d_in[8];
    float* out = (float*)d_out;

    float *qb, *kb, *vb, *ob;
    cudaGetSymbolAddress((void**)&qb, g_Q);
    cudaGetSymbolAddress((void**)&kb, g_K);
    cudaGetSymbolAddress((void**)&vb, g_V);
    cudaGetSymbolAddress((void**)&ob, g_O);

    dim3 ggrid(H_ / 128, M_ / 128);   // (16, 32)
    gemm_bias_kernel<<<ggrid, 256>>>(X, Wq, bq, qb, M_, H_, H_);
    gemm_bias_kernel<<<ggrid, 256>>>(X, Wk, bk, kb, M_, H_, H_);
    gemm_bias_kernel<<<ggrid, 256>>>(X, Wv, bv, vb, M_, H_, H_);

    int smem = ATTN_SMEM_FLOATS * 4;  // 115456 bytes
    cudaFuncSetAttribute(attn_kernel,
                         cudaFuncAttributeMaxDynamicSharedMemorySize, smem);
    dim3 agrid(S_ / BQ, B_ * NH_);    // (32, 32)
    attn_kernel<<<agrid, 256, smem>>>(qb, kb, vb, ob);

    gemm_bias_kernel<<<ggrid, 256>>>(ob, Wo, bo, out, M_, H_, H_);
}

// round 7
// speedup vs baseline: 1.7246x; 1.7246x over previous
#include <cuda_runtime.h>
#include <cuda_bf16.h>
#include <cstdint>

#define B_  2
#define S_  2048
#define H_  2048
#define NH_ 16
#define HD_ 128
#define M_  (B_ * S_)      // 4096 rows
#define K3_ (3 * H_)       // 6144 (hi|hi|lo split columns)
#define BKG 64             // GEMM k-tile (bf16 elems) = 128 B/row
#define NT_ (K3_ / BKG)    // 96 k-iterations

// ---------------------------------------------------------------------------
// Scratch (__device__ globals: allocation-free rule)
// ---------------------------------------------------------------------------
__device__ float g_Q[(size_t)M_ * H_];
__device__ float g_K[(size_t)M_ * H_];
__device__ float g_V[(size_t)M_ * H_];
__device__ float g_O[(size_t)M_ * H_];
__device__ __nv_bfloat16 g_A3[(size_t)M_ * K3_];   // split activations
__device__ __nv_bfloat16 g_W3[(size_t)H_ * K3_];   // split weights (reused)

// ---------------------------------------------------------------------------
// Helpers (all compute_103-legal PTX: cp.async, ldmatrix, mma.sync)
// ---------------------------------------------------------------------------
__device__ __forceinline__ uint32_t smem_u32(const void* p) {
    uint32_t a;
    asm("{ .reg .u64 t; cvta.to.shared.u64 t, %1; cvt.u32.u64 %0, t; }"
        : "=r"(a) : "l"(p));
    return a;
}
__device__ __forceinline__ void cp16(uint32_t s, const void* g) {
    asm volatile("cp.async.cg.shared.global [%0], [%1], 16;"
                 :: "r"(s), "l"(g) : "memory");
}
#define CP_COMMIT() asm volatile("cp.async.commit_group;" ::: "memory")
#define CP_WAIT(N)  asm volatile("cp.async.wait_group %0;" :: "n"(N) : "memory")

__device__ __forceinline__ void ldsm_x4(uint32_t r[4], uint32_t addr) {
    asm volatile("ldmatrix.sync.aligned.m8n8.x4.shared.b16 {%0,%1,%2,%3}, [%4];"
                 : "=r"(r[0]), "=r"(r[1]), "=r"(r[2]), "=r"(r[3]) : "r"(addr));
}
__device__ __forceinline__ void mma_bf16(float d[4], const uint32_t a[4],
                                         uint32_t b0, uint32_t b1) {
    asm volatile(
        "mma.sync.aligned.m16n8k16.row.col.f32.bf16.bf16.f32 "
        "{%0,%1,%2,%3}, {%4,%5,%6,%7}, {%8,%9}, {%0,%1,%2,%3};"
        : "+f"(d[0]), "+f"(d[1]), "+f"(d[2]), "+f"(d[3])
        : "r"(a[0]), "r"(a[1]), "r"(a[2]), "r"(a[3]), "r"(b0), "r"(b1));
}

// ---------------------------------------------------------------------------
// Split kernel: X[rows,H] fp32 -> Y[rows,3H] bf16.
//   wpat=0 (activations): cols [0,H)=hi, [H,2H)=hi, [2H,3H)=lo
//   wpat=1 (weights):     cols [0,H)=hi, [H,2H)=lo, [2H,3H)=hi
// Pairing over shared k'-columns gives hi*hi + hi*lo + lo*hi.
// ---------------------------------------------------------------------------
__global__ void __launch_bounds__(256)
split3_kernel(const float* __restrict__ X, __nv_bfloat16* __restrict__ Y,
              int nrows, int wpat)
{
    int t   = blockIdx.x * 256 + threadIdx.x;
    int row = t >> 9;          // H_/4 = 512 float4 per row
    int k4  = t & 511;
    if (row >= nrows) return;
    float4 x = *(const float4*)(X + (size_t)row * H_ + k4 * 4);
    __nv_bfloat16 h0 = __float2bfloat16_rn(x.x);
    __nv_bfloat16 h1 = __float2bfloat16_rn(x.y);
    __nv_bfloat16 h2 = __float2bfloat16_rn(x.z);
    __nv_bfloat16 h3 = __float2bfloat16_rn(x.w);
    __nv_bfloat16 l0 = __float2bfloat16_rn(x.x - __bfloat162float(h0));
    __nv_bfloat16 l1 = __float2bfloat16_rn(x.y - __bfloat162float(h1));
    __nv_bfloat16 l2 = __float2bfloat16_rn(x.z - __bfloat162float(h2));
    __nv_bfloat16 l3 = __float2bfloat16_rn(x.w - __bfloat162float(h3));
    __nv_bfloat162 ha = __halves2bfloat162(h0, h1);
    __nv_bfloat162 hb = __halves2bfloat162(h2, h3);
    __nv_bfloat162 la = __halves2bfloat162(l0, l1);
    __nv_bfloat162 lb = __halves2bfloat162(l2, l3);
    __nv_bfloat16* out = Y + (size_t)row * K3_ + k4 * 4;
    *(__nv_bfloat162*)(out + 0) = ha;
    *(__nv_bfloat162*)(out + 2) = hb;
    if (wpat) {
        *(__nv_bfloat162*)(out + H_)         = la;
        *(__nv_bfloat162*)(out + H_ + 2)     = lb;
        *(__nv_bfloat162*)(out + 2 * H_)     = ha;
        *(__nv_bfloat162*)(out + 2 * H_ + 2) = hb;
    } else {
        *(__nv_bfloat162*)(out + H_)         = ha;
        *(__nv_bfloat162*)(out + H_ + 2)     = hb;
        *(__nv_bfloat162*)(out + 2 * H_)     = la;
        *(__nv_bfloat162*)(out + 2 * H_ + 2) = lb;
    }
}

// ---------------------------------------------------------------------------
// mma.sync bf16 GEMM: C[M,N] = A3[M,K3] @ W3[N,K3]^T + bias
// 128x128 CTA tile, BK=64, 8 warps (2x4), warp tile 64x32, cp.async double buf.
// smem buffer: A 128x128B swizzled + B 128x128B swizzled, x2 buffers = 64 KB.
// ---------------------------------------------------------------------------
#define GEMM_SMEM 65536

__global__ void __launch_bounds__(256)
mma_gemm_kernel(const __nv_bfloat16* __restrict__ A3,
                const __nv_bfloat16* __restrict__ W3,
                const float* __restrict__ bias,
                float* __restrict__ C)
{
    extern __shared__ __align__(128) char smem[];
    const uint32_t sb   = smem_u32(smem);
    const int tid    = threadIdx.x;
    const int wid    = tid >> 5;
    const int lane   = tid & 31;
    const int warp_m = wid >> 2;     // 0..1 -> 64-row slab
    const int warp_n = wid & 3;      // 0..3 -> 32-col slab
    const int m0 = blockIdx.y * 128;
    const int n0 = blockIdx.x * 128;

    const __nv_bfloat16* Ag = A3 + (size_t)m0 * K3_;
    const __nv_bfloat16* Bg = W3 + (size_t)n0 * K3_;

    float d[4][4][4];
#pragma unroll
    for (int i = 0; i < 4; i++)
#pragma unroll
        for (int j = 0; j < 4; j++)
#pragma unroll
            for (int k = 0; k < 4; k++) d[i][j][k] = 0.f;

    // ---- gmem -> smem loader (cp.async, SW128 xor swizzle) ----
    auto load = [&](int it, int buf) {
        uint32_t base = sb + buf * 32768;
#pragma unroll
        for (int l = 0; l < 4; l++) {
            int idx = tid + l * 256;        // 0..1023
            int r   = idx >> 3;             // row 0..127
            int c   = idx & 7;              // 16B chunk 0..7
            uint32_t sw = (uint32_t)r * 128 + ((c ^ (r & 7)) * 16);
            cp16(base + sw,          Ag + (size_t)r * K3_ + it * BKG + c * 8);
            cp16(base + 16384 + sw,  Bg + (size_t)r * K3_ + it * BKG + c * 8);
        }
        CP_COMMIT();
    };

    load(0, 0);

    for (int it = 0; it < NT_; it++) {
        const int buf = it & 1;
        if (it + 1 < NT_) { load(it + 1, buf ^ 1); CP_WAIT(1); }
        else              { CP_WAIT(0); }
        __syncthreads();

        const uint32_t Ab = sb + buf * 32768;
        const uint32_t Bb = Ab + 16384;

#pragma unroll
        for (int ks = 0; ks < 4; ks++) {   // 4 x k16 steps cover BK=64
            uint32_t a[4][4];
#pragma unroll
            for (int mi = 0; mi < 4; mi++) {
                int row = warp_m * 64 + mi * 16 + (lane & 15);
                int ch  = 2 * ks + (lane >> 4);
                ldsm_x4(a[mi], Ab + (uint32_t)row * 128 + ((ch ^ (row & 7)) * 16));
            }
            uint32_t b[2][4];
#pragma unroll
            for (int j2 = 0; j2 < 2; j2++) {
                int row = warp_n * 32 + j2 * 16 + (lane & 7) + ((lane >> 4) << 3);
                int ch  = 2 * ks + ((lane >> 3) & 1);
                ldsm_x4(b[j2], Bb + (uint32_t)row * 128 + ((ch ^ (row & 7)) * 16));
            }
#pragma unroll
            for (int mi = 0; mi < 4; mi++)
#pragma unroll
                for (int j2 = 0; j2 < 2; j2++) {
                    mma_bf16(d[mi][2 * j2],     a[mi], b[j2][0], b[j2][1]);
                    mma_bf16(d[mi][2 * j2 + 1], a[mi], b[j2][2], b[j2][3]);
                }
        }
        __syncthreads();
    }

    // ---- epilogue: +bias, float2 stores ----
#pragma unroll
    for (int mi = 0; mi < 4; mi++) {
        int r0 = m0 + warp_m * 64 + mi * 16 + (lane >> 2);
#pragma unroll
        for (int ni = 0; ni < 4; ni++) {
            int cc = n0 + warp_n * 32 + ni * 8 + (lane & 3) * 2;
            float2 bv = *(const float2*)&bias[cc];
            float2 o0, o1;
            o0.x = d[mi][ni][0] + bv.x; o0.y = d[mi][ni][1] + bv.y;
            o1.x = d[mi][ni][2] + bv.x; o1.y = d[mi][ni][3] + bv.y;
            *(float2*)&C[(size_t)r0 * H_ + cc]       = o0;
            *(float2*)&C[(size_t)(r0 + 8) * H_ + cc] = o1;
        }
    }
}

// ---------------------------------------------------------------------------
// Flash-style fp32 attention (unchanged; ported to mma next round)
// ---------------------------------------------------------------------------
#define BQ     64
#define BKT    64
#define KS_STR 129
#define PS_STR 66
#define ATTN_SMEM_FLOATS (8192 + 8256 + 8192 + 4224)

__global__ void __launch_bounds__(256, 2)
attn_kernel(const float* __restrict__ Q, const float* __restrict__ K,
            const float* __restrict__ V, float* __restrict__ O)
{
    extern __shared__ float sm[];
    float* Qs = sm;             // [64][128]
    float* Ks = Qs + 8192;      // [64][129]
    float* Vs = Ks + 8256;      // [64][128]
    float* Ps = Vs + 8192;      // [64][66]

    const int tid = threadIdx.x;
    const int tx  = tid & 15;
    const int ty  = tid >> 4;
    const int bh  = blockIdx.y;
    const int b   = bh >> 4;
    const int h   = bh & 15;
    const int q0  = blockIdx.x * BQ;

    const size_t off = (size_t)b * S_ * H_ + (size_t)h * HD_;
    const float* Qg = Q + off;
    const float* Kg = K + off;
    const float* Vg = V + off;
    float*       Og = O + off;

    const float scale = 0.08838834764831845f;  // 1/sqrt(128)

#pragma unroll
    for (int l = 0; l < 8; l++) {
        int idx = tid + l * 256;
        int r   = idx >> 5;
        int c4  = (idx & 31);
        float4 v = *(const float4*)&Qg[(size_t)(q0 + r) * H_ + c4 * 4];
        v.x *= scale; v.y *= scale; v.z *= scale; v.w *= scale;
        *(float4*)&Qs[r * 128 + c4 * 4] = v;
    }

    float m_i[4], l_i[4], acc[4][8];
#pragma unroll
    for (int i = 0; i < 4; i++) {
        m_i[i] = -1e30f; l_i[i] = 0.f;
#pragma unroll
        for (int j = 0; j < 8; j++) acc[i][j] = 0.f;
    }

    for (int kt = 0; kt < S_; kt += BKT) {
        __syncthreads();
#pragma unroll
        for (int l = 0; l < 8; l++) {
            int idx = tid + l * 256;
            int r   = idx >> 5;
            int c   = (idx & 31) * 4;
            float4 kv = *(const float4*)&Kg[(size_t)(kt + r) * H_ + c];
            Ks[r * KS_STR + c + 0] = kv.x; Ks[r * KS_STR + c + 1] = kv.y;
            Ks[r * KS_STR + c + 2] = kv.z; Ks[r * KS_STR + c + 3] = kv.w;
            float4 vv = *(const float4*)&Vg[(size_t)(kt + r) * H_ + c];
            *(float4*)&Vs[r * 128 + c] = vv;
        }
        __syncthreads();

        float s[4][4];
#pragma unroll
        for (int i = 0; i < 4; i++)
#pragma unroll
            for (int j = 0; j < 4; j++) s[i][j] = 0.f;

        const float4* Qs4 = (const float4*)Qs;
#pragma unroll 2
        for (int d4 = 0; d4 < 32; d4++) {
            float4 a4[4];
#pragma unroll
            for (int i = 0; i < 4; i++) a4[i] = Qs4[(ty * 4 + i) * 32 + d4];
#pragma unroll
            for (int dd = 0; dd < 4; dd++) {
                float b_[4];
#pragma unroll
                for (int j = 0; j < 4; j++)
                    b_[j] = Ks[(tx + 16 * j) * KS_STR + d4 * 4 + dd];
#pragma unroll
                for (int i = 0; i < 4; i++) {
                    float av = ((const float*)&a4[i])[dd];
#pragma unroll
                    for (int j = 0; j < 4; j++)
                        s[i][j] = fmaf(av, b_[j], s[i][j]);
                }
            }
        }

#pragma unroll
        for (int i = 0; i < 4; i++) {
            float mx = fmaxf(fmaxf(s[i][0], s[i][1]), fmaxf(s[i][2], s[i][3]));
#pragma unroll
            for (int o = 8; o > 0; o >>= 1)
                mx = fmaxf(mx, __shfl_xor_sync(0xffffffffu, mx, o));
            float mn    = fmaxf(m_i[i], mx);
            float alpha = __expf(m_i[i] - mn);
            m_i[i] = mn;
            float ls = 0.f;
#pragma unroll
            for (int j = 0; j < 4; j++) {
                float p = __expf(s[i][j] - mn);
                s[i][j] = p;
                ls += p;
            }
#pragma unroll
            for (int o = 8; o > 0; o >>= 1)
                ls += __shfl_xor_sync(0xffffffffu, ls, o);
            l_i[i] = l_i[i] * alpha + ls;
#pragma unroll
            for (int j = 0; j < 8; j++) acc[i][j] *= alpha;
#pragma unroll
            for (int j = 0; j < 4; j++)
                Ps[(ty * 4 + i) * PS_STR + tx + 16 * j] = s[i][j];
        }
        __syncthreads();

        const float4* Vs4 = (const float4*)Vs;
#pragma unroll 4
        for (int kk = 0; kk < BKT; kk++) {
            float4 v0 = Vs4[kk * 32 + tx * 2];
            float4 v1 = Vs4[kk * 32 + tx * 2 + 1];
#pragma unroll
            for (int i = 0; i < 4; i++) {
                float p = Ps[(ty * 4 + i) * PS_STR + kk];
                acc[i][0] = fmaf(p, v0.x, acc[i][0]);
                acc[i][1] = fmaf(p, v0.y, acc[i][1]);
                acc[i][2] = fmaf(p, v0.z, acc[i][2]);
                acc[i][3] = fmaf(p, v0.w, acc[i][3]);
                acc[i][4] = fmaf(p, v1.x, acc[i][4]);
                acc[i][5] = fmaf(p, v1.y, acc[i][5]);
                acc[i][6] = fmaf(p, v1.z, acc[i][6]);
                acc[i][7] = fmaf(p, v1.w, acc[i][7]);
            }
        }
    }

#pragma unroll
    for (int i = 0; i < 4; i++) {
        float inv = 1.f / l_i[i];
        int r = q0 + ty * 4 + i;
        float4 o0, o1;
        o0.x = acc[i][0] * inv; o0.y = acc[i][1] * inv;
        o0.z = acc[i][2] * inv; o0.w = acc[i][3] * inv;
        o1.x = acc[i][4] * inv; o1.y = acc[i][5] * inv;
        o1.z = acc[i][6] * inv; o1.w = acc[i][7] * inv;
        *(float4*)&Og[(size_t)r * H_ + tx * 8]     = o0;
        *(float4*)&Og[(size_t)r * H_ + tx * 8 + 4] = o1;
    }
}

// ---------------------------------------------------------------------------
// kernel_launch
// ---------------------------------------------------------------------------
extern "C" void kernel_launch(void* const* d_in, const int* in_sizes, int n_in,
                              void* d_out, int out_size)
{
    const float* X  = (const float*)d_in[0];
    const float* Wq = (const float*)d_in[1];
    const float* bq = (const float*)d_in[2];
    const float* Wk = (const float*)d_in[3];
    const float* bk = (const float*)d_in[4];
    const float* Wv = (const float*)d_in[5];
    const float* bv = (const float*)d_in[6];
    const float* Wo = (const float*)d_in[7];
    const float* bo = (const float*)d_in[8];
    float* out = (float*)d_out;

    float *qb, *kb, *vb, *ob;
    __nv_bfloat16 *a3, *w3;
    cudaGetSymbolAddress((void**)&qb, g_Q);
    cudaGetSymbolAddress((void**)&kb, g_K);
    cudaGetSymbolAddress((void**)&vb, g_V);
    cudaGetSymbolAddress((void**)&ob, g_O);
    cudaGetSymbolAddress((void**)&a3, g_A3);
    cudaGetSymbolAddress((void**)&w3, g_W3);

    cudaFuncSetAttribute(mma_gemm_kernel,
                         cudaFuncAttributeMaxDynamicSharedMemorySize, GEMM_SMEM);

    const int splitA_blocks = (M_ * (H_ / 4)) / 256;  // 8192
    const int splitW_blocks = (H_ * (H_ / 4)) / 256;  // 4096
    dim3 ggrid(H_ / 128, M_ / 128);                   // (16, 32)

    // QKV projections on mma.sync bf16 (3-term split)
    split3_kernel<<<splitA_blocks, 256>>>(X, a3, M_, 0);
    split3_kernel<<<splitW_blocks, 256>>>(Wq, w3, H_, 1);
    mma_gemm_kernel<<<ggrid, 256, GEMM_SMEM>>>(a3, w3, bq, qb);
    split3_kernel<<<splitW_blocks, 256>>>(Wk, w3, H_, 1);
    mma_gemm_kernel<<<ggrid, 256, GEMM_SMEM>>>(a3, w3, bk, kb);
    split3_kernel<<<splitW_blocks, 256>>>(Wv, w3, H_, 1);
    mma_gemm_kernel<<<ggrid, 256, GEMM_SMEM>>>(a3, w3, bv, vb);

    // attention (fp32)
    int smem = ATTN_SMEM_FLOATS * 4;
    cudaFuncSetAttribute(attn_kernel,
                         cudaFuncAttributeMaxDynamicSharedMemorySize, smem);
    dim3 agrid(S_ / BQ, B_ * NH_);
    attn_kernel<<<agrid, 256, smem>>>(qb, kb, vb, ob);

    // output projection
    split3_kernel<<<splitA_blocks, 256>>>(ob, a3, M_, 0);
    split3_kernel<<<splitW_blocks, 256>>>(Wo, w3, H_, 1);
    mma_gemm_kernel<<<ggrid, 256, GEMM_SMEM>>>(a3, w3, bo, out);
}

// round 10
// speedup vs baseline: 3.9344x; 2.2813x over previous
#include <cuda_runtime.h>
#include <cuda_bf16.h>
#include <cuda_fp16.h>
#include <cstdint>

#define B_  2
#define S_  2048
#define H_  2048
#define NH_ 16
#define HD_ 128
#define M_  (B_ * S_)      // 4096 rows
#define K3_ (3 * H_)       // 6144 (hi|hi|lo split columns)
#define BKG 64             // GEMM k-tile (bf16 elems) = 128 B/row
#define NT_ (K3_ / BKG)    // 96 k-iterations

// ---------------------------------------------------------------------------
// Scratch (__device__ globals: allocation-free rule)
// ---------------------------------------------------------------------------
__device__ __half g_Qh[(size_t)M_ * H_];
__device__ __half g_Kh[(size_t)M_ * H_];
__device__ __half g_Vh[(size_t)M_ * H_];
__device__ float  g_O [(size_t)M_ * H_];
__device__ __nv_bfloat16 g_A3[(size_t)M_ * K3_];   // split activations
__device__ __nv_bfloat16 g_W3[(size_t)H_ * K3_];   // split weights (reused)

// ---------------------------------------------------------------------------
// Helpers (compute_103-legal PTX: cp.async, ldmatrix, mma.sync)
// ---------------------------------------------------------------------------
__device__ __forceinline__ uint32_t smem_u32(const void* p) {
    uint32_t a;
    asm("{ .reg .u64 t; cvta.to.shared.u64 t, %1; cvt.u32.u64 %0, t; }"
        : "=r"(a) : "l"(p));
    return a;
}
__device__ __forceinline__ void cp16(uint32_t s, const void* g) {
    asm volatile("cp.async.cg.shared.global [%0], [%1], 16;"
                 :: "r"(s), "l"(g) : "memory");
}
#define CP_COMMIT() asm volatile("cp.async.commit_group;" ::: "memory")
#define CP_WAIT(N)  asm volatile("cp.async.wait_group %0;" :: "n"(N) : "memory")

__device__ __forceinline__ void ldsm_x4(uint32_t r[4], uint32_t addr) {
    asm volatile("ldmatrix.sync.aligned.m8n8.x4.shared.b16 {%0,%1,%2,%3}, [%4];"
                 : "=r"(r[0]), "=r"(r[1]), "=r"(r[2]), "=r"(r[3]) : "r"(addr));
}
__device__ __forceinline__ void ldsm_x4_t(uint32_t r[4], uint32_t addr) {
    asm volatile("ldmatrix.sync.aligned.m8n8.x4.trans.shared.b16 {%0,%1,%2,%3}, [%4];"
                 : "=r"(r[0]), "=r"(r[1]), "=r"(r[2]), "=r"(r[3]) : "r"(addr));
}
__device__ __forceinline__ void mma_bf16(float d[4], const uint32_t a[4],
                                         uint32_t b0, uint32_t b1) {
    asm volatile(
        "mma.sync.aligned.m16n8k16.row.col.f32.bf16.bf16.f32 "
        "{%0,%1,%2,%3}, {%4,%5,%6,%7}, {%8,%9}, {%0,%1,%2,%3};"
        : "+f"(d[0]), "+f"(d[1]), "+f"(d[2]), "+f"(d[3])
        : "r"(a[0]), "r"(a[1]), "r"(a[2]), "r"(a[3]), "r"(b0), "r"(b1));
}
__device__ __forceinline__ void mma_f16(float d[4], const uint32_t a[4],
                                        uint32_t b0, uint32_t b1) {
    asm volatile(
        "mma.sync.aligned.m16n8k16.row.col.f32.f16.f16.f32 "
        "{%0,%1,%2,%3}, {%4,%5,%6,%7}, {%8,%9}, {%0,%1,%2,%3};"
        : "+f"(d[0]), "+f"(d[1]), "+f"(d[2]), "+f"(d[3])
        : "r"(a[0]), "r"(a[1]), "r"(a[2]), "r"(a[3]), "r"(b0), "r"(b1));
}
__device__ __forceinline__ uint32_t pack_h2(float lo, float hi) {
    uint32_t u;
    asm("cvt.rn.f16x2.f32 %0, %1, %2;" : "=r"(u) : "f"(hi), "f"(lo));
    return u;
}
// FFMA-only exp2 (no MUFU): round via magic number, deg-4 Taylor on [-0.5,0.5],
// exponent splice. Rel err ~4e-5; valid for t <= ~0 (clamped at -120).
__device__ __forceinline__ float fexp2(float t) {
    t = fmaxf(t, -120.f);
    float z = t + 12582912.f;                   // 1.5*2^23: round-to-nearest
    int   k = __float_as_int(z) - 0x4B400000;
    float r = t - (z - 12582912.f);             // r in [-0.5, 0.5]
    float p = 1.f + r * (0.69314718f + r * (0.24022651f +
                   r * (0.05550411f + r * 0.00961813f)));
    return __int_as_float(__float_as_int(p) + (k << 23));
}

// ---------------------------------------------------------------------------
// Split kernel: X[rows,H] fp32 -> Y[rows,3H] bf16 (hi/lo 3-term split).
// ---------------------------------------------------------------------------
__global__ void __launch_bounds__(256)
split3_kernel(const float* __restrict__ X, __nv_bfloat16* __restrict__ Y,
              int nrows, int wpat)
{
    int t   = blockIdx.x * 256 + threadIdx.x;
    int row = t >> 9;
    int k4  = t & 511;
    if (row >= nrows) return;
    float4 x = *(const float4*)(X + (size_t)row * H_ + k4 * 4);
    __nv_bfloat16 h0 = __float2bfloat16_rn(x.x);
    __nv_bfloat16 h1 = __float2bfloat16_rn(x.y);
    __nv_bfloat16 h2 = __float2bfloat16_rn(x.z);
    __nv_bfloat16 h3 = __float2bfloat16_rn(x.w);
    __nv_bfloat16 l0 = __float2bfloat16_rn(x.x - __bfloat162float(h0));
    __nv_bfloat16 l1 = __float2bfloat16_rn(x.y - __bfloat162float(h1));
    __nv_bfloat16 l2 = __float2bfloat16_rn(x.z - __bfloat162float(h2));
    __nv_bfloat16 l3 = __float2bfloat16_rn(x.w - __bfloat162float(h3));
    __nv_bfloat162 ha = __halves2bfloat162(h0, h1);
    __nv_bfloat162 hb = __halves2bfloat162(h2, h3);
    __nv_bfloat162 la = __halves2bfloat162(l0, l1);
    __nv_bfloat162 lb = __halves2bfloat162(l2, l3);
    __nv_bfloat16* out = Y + (size_t)row * K3_ + k4 * 4;
    *(__nv_bfloat162*)(out + 0) = ha;
    *(__nv_bfloat162*)(out + 2) = hb;
    if (wpat) {
        *(__nv_bfloat162*)(out + H_)         = la;
        *(__nv_bfloat162*)(out + H_ + 2)     = lb;
        *(__nv_bfloat162*)(out + 2 * H_)     = ha;
        *(__nv_bfloat162*)(out + 2 * H_ + 2) = hb;
    } else {
        *(__nv_bfloat162*)(out + H_)         = ha;
        *(__nv_bfloat162*)(out + H_ + 2)     = hb;
        *(__nv_bfloat162*)(out + 2 * H_)     = la;
        *(__nv_bfloat162*)(out + 2 * H_ + 2) = lb;
    }
}

// ---------------------------------------------------------------------------
// mma.sync bf16 GEMM: C = A3 @ W3^T + bias. Epilogue: fp32 (Cf) or fp16 (Ch).
// ---------------------------------------------------------------------------
#define GEMM_SMEM 65536

__global__ void __launch_bounds__(256)
mma_gemm_kernel(const __nv_bfloat16* __restrict__ A3,
                const __nv_bfloat16* __restrict__ W3,
                const float* __restrict__ bias,
                float* __restrict__ Cf, __half* __restrict__ Ch)
{
    extern __shared__ __align__(128) char smem[];
    const uint32_t sb   = smem_u32(smem);
    const int tid    = threadIdx.x;
    const int wid    = tid >> 5;
    const int lane   = tid & 31;
    const int warp_m = wid >> 2;
    const int warp_n = wid & 3;
    const int m0 = blockIdx.y * 128;
    const int n0 = blockIdx.x * 128;

    const __nv_bfloat16* Ag = A3 + (size_t)m0 * K3_;
    const __nv_bfloat16* Bg = W3 + (size_t)n0 * K3_;

    float d[4][4][4];
#pragma unroll
    for (int i = 0; i < 4; i++)
#pragma unroll
        for (int j = 0; j < 4; j++)
#pragma unroll
            for (int k = 0; k < 4; k++) d[i][j][k] = 0.f;

    auto load = [&](int it, int buf) {
        uint32_t base = sb + buf * 32768;
#pragma unroll
        for (int l = 0; l < 4; l++) {
            int idx = tid + l * 256;
            int r   = idx >> 3;
            int c   = idx & 7;
            uint32_t sw = (uint32_t)r * 128 + ((c ^ (r & 7)) * 16);
            cp16(base + sw,          Ag + (size_t)r * K3_ + it * BKG + c * 8);
            cp16(base + 16384 + sw,  Bg + (size_t)r * K3_ + it * BKG + c * 8);
        }
        CP_COMMIT();
    };

    load(0, 0);

    for (int it = 0; it < NT_; it++) {
        const int buf = it & 1;
        if (it + 1 < NT_) { load(it + 1, buf ^ 1); CP_WAIT(1); }
        else              { CP_WAIT(0); }
        __syncthreads();

        const uint32_t Ab = sb + buf * 32768;
        const uint32_t Bb = Ab + 16384;

#pragma unroll
        for (int ks = 0; ks < 4; ks++) {
            uint32_t a[4][4];
#pragma unroll
            for (int mi = 0; mi < 4; mi++) {
                int row = warp_m * 64 + mi * 16 + (lane & 15);
                int ch  = 2 * ks + (lane >> 4);
                ldsm_x4(a[mi], Ab + (uint32_t)row * 128 + ((ch ^ (row & 7)) * 16));
            }
            uint32_t b[2][4];
#pragma unroll
            for (int j2 = 0; j2 < 2; j2++) {
                int row = warp_n * 32 + j2 * 16 + (lane & 7) + ((lane >> 4) << 3);
                int ch  = 2 * ks + ((lane >> 3) & 1);
                ldsm_x4(b[j2], Bb + (uint32_t)row * 128 + ((ch ^ (row & 7)) * 16));
            }
#pragma unroll
            for (int mi = 0; mi < 4; mi++)
#pragma unroll
                for (int j2 = 0; j2 < 2; j2++) {
                    mma_bf16(d[mi][2 * j2],     a[mi], b[j2][0], b[j2][1]);
                    mma_bf16(d[mi][2 * j2 + 1], a[mi], b[j2][2], b[j2][3]);
                }
        }
        __syncthreads();
    }

#pragma unroll
    for (int mi = 0; mi < 4; mi++) {
        int r0 = m0 + warp_m * 64 + mi * 16 + (lane >> 2);
#pragma unroll
        for (int ni = 0; ni < 4; ni++) {
            int cc = n0 + warp_n * 32 + ni * 8 + (lane & 3) * 2;
            float2 bv = *(const float2*)&bias[cc];
            float v00 = d[mi][ni][0] + bv.x, v01 = d[mi][ni][1] + bv.y;
            float v10 = d[mi][ni][2] + bv.x, v11 = d[mi][ni][3] + bv.y;
            if (Ch) {
                *(__half2*)&Ch[(size_t)r0 * H_ + cc]       = __floats2half2_rn(v00, v01);
                *(__half2*)&Ch[(size_t)(r0 + 8) * H_ + cc] = __floats2half2_rn(v10, v11);
            } else {
                *(float2*)&Cf[(size_t)r0 * H_ + cc]       = make_float2(v00, v01);
                *(float2*)&Cf[(size_t)(r0 + 8) * H_ + cc] = make_float2(v10, v11);
            }
        }
    }
}

// ---------------------------------------------------------------------------
// FA2-style fp16 mma attention. CTA: 128 q-rows x one (b,h). 8 warps x 16 rows.
// Q resident in smem (32KB); K/V 64-row tiles double-buffered (64KB).
// S-frag -> P a-frag register identity; V via ldmatrix.trans; fp32 accum.
// exp via FFMA-only fexp2 (MUFU avoided).
// ---------------------------------------------------------------------------
#define ATTN_SMEM 98304

__global__ void __launch_bounds__(256)
attn_mma_kernel(const __half* __restrict__ Qh, const __half* __restrict__ Kh,
                const __half* __restrict__ Vh, float* __restrict__ O)
{
    extern __shared__ __align__(128) char smem[];
    const uint32_t sb  = smem_u32(smem);
    const uint32_t Qs  = sb;            // 128 rows x 256 B
    const uint32_t KVs = sb + 32768;    // 2 x (K 16KB + V 16KB)

    const int tid  = threadIdx.x;
    const int wid  = tid >> 5;
    const int lane = tid & 31;
    const int g    = lane >> 2;
    const int t4   = lane & 3;
    const int bh = blockIdx.y;
    const int b  = bh >> 4;
    const int h  = bh & 15;
    const int q0 = blockIdx.x * 128;

    const __half* Qg = Qh + ((size_t)(b * S_) + q0) * H_ + h * HD_;
    const __half* Kg = Kh + (size_t)(b * S_) * H_ + h * HD_;
    const __half* Vg = Vh + (size_t)(b * S_) * H_ + h * HD_;

    // Q tile: 128 rows x 16 chunks (16B), xor-swizzled
#pragma unroll
    for (int l = 0; l < 8; l++) {
        int idx = tid + l * 256;
        int r = idx >> 4, c = idx & 15;
        cp16(Qs + r * 256 + ((c ^ (r & 7)) * 16), Qg + (size_t)r * H_ + c * 8);
    }

    auto loadKV = [&](int kt, int buf) {
        uint32_t base = KVs + buf * 32768;
#pragma unroll
        for (int l = 0; l < 4; l++) {
            int idx = tid + l * 256;
            int r = idx >> 4, c = idx & 15;
            uint32_t sw = (uint32_t)r * 256 + ((c ^ (r & 7)) * 16);
            cp16(base + sw,         Kg + (size_t)(kt * 64 + r) * H_ + c * 8);
            cp16(base + 16384 + sw, Vg + (size_t)(kt * 64 + r) * H_ + c * 8);
        }
        CP_COMMIT();
    };
    loadKV(0, 0);   // group 0 = Q + KV0

    float o[16][4];
#pragma unroll
    for (int n = 0; n < 16; n++)
#pragma unroll
        for (int k = 0; k < 4; k++) o[n][k] = 0.f;
    float m0 = -1e30f, m1 = -1e30f, l0 = 0.f, l1 = 0.f;
    const float cexp = 0.08838834764831845f * 1.4426950408889634f;  // scale*log2e

    const int NIT = S_ / 64;   // 32
    for (int it = 0; it < NIT; it++) {
        const int buf = it & 1;
        if (it + 1 < NIT) { loadKV(it + 1, buf ^ 1); CP_WAIT(1); }
        else              { CP_WAIT(0); }
        __syncthreads();
        const uint32_t Kb = KVs + buf * 32768;
        const uint32_t Vb = Kb + 16384;

        // ---- S = Q @ K^T : 16 q-rows x 64 keys per warp ----
        float s[8][4];
#pragma unroll
        for (int j = 0; j < 8; j++)
#pragma unroll
            for (int k = 0; k < 4; k++) s[j][k] = 0.f;

#pragma unroll
        for (int ks = 0; ks < 8; ks++) {
            uint32_t a[4];
            {
                int row = wid * 16 + (lane & 15);
                int ch  = 2 * ks + (lane >> 4);
                ldsm_x4(a, Qs + (uint32_t)row * 256 + ((ch ^ (row & 7)) * 16));
            }
#pragma unroll
            for (int j2 = 0; j2 < 4; j2++) {
                uint32_t bb[4];
                int row = j2 * 16 + (lane & 7) + ((lane >> 4) << 3);
                int ch  = 2 * ks + ((lane >> 3) & 1);
                ldsm_x4(bb, Kb + (uint32_t)row * 256 + ((ch ^ (row & 7)) * 16));
                mma_f16(s[2 * j2],     a, bb[0], bb[1]);
                mma_f16(s[2 * j2 + 1], a, bb[2], bb[3]);
            }
        }

        // ---- online softmax (rows g and g+8; quad = lanes sharing g) ----
        float mx0 = s[0][0], mx1 = s[0][2];
#pragma unroll
        for (int j = 0; j < 8; j++) {
            mx0 = fmaxf(mx0, fmaxf(s[j][0], s[j][1]));
            mx1 = fmaxf(mx1, fmaxf(s[j][2], s[j][3]));
        }
        mx0 = fmaxf(mx0, __shfl_xor_sync(0xffffffffu, mx0, 1));
        mx0 = fmaxf(mx0, __shfl_xor_sync(0xffffffffu, mx0, 2));
        mx1 = fmaxf(mx1, __shfl_xor_sync(0xffffffffu, mx1, 1));
        mx1 = fmaxf(mx1, __shfl_xor_sync(0xffffffffu, mx1, 2));
        float nm0 = fmaxf(m0, mx0), nm1 = fmaxf(m1, mx1);
        float al0 = fexp2((m0 - nm0) * cexp);
        float al1 = fexp2((m1 - nm1) * cexp);
        m0 = nm0; m1 = nm1;

        float rs0 = 0.f, rs1 = 0.f;
        uint32_t ph[8], ph2[8];
#pragma unroll
        for (int j = 0; j < 8; j++) {
            float p0 = fexp2((s[j][0] - nm0) * cexp);
            float p1 = fexp2((s[j][1] - nm0) * cexp);
            float p2 = fexp2((s[j][2] - nm1) * cexp);
            float p3 = fexp2((s[j][3] - nm1) * cexp);
            rs0 += p0 + p1; rs1 += p2 + p3;
            ph[j]  = pack_h2(p0, p1);
            ph2[j] = pack_h2(p2, p3);
        }
        l0 = l0 * al0 + rs0;
        l1 = l1 * al1 + rs1;
#pragma unroll
        for (int n = 0; n < 16; n++) {
            o[n][0] *= al0; o[n][1] *= al0;
            o[n][2] *= al1; o[n][3] *= al1;
        }

        // ---- O += P @ V : k = 64 keys (4 k16 steps), n = 128 hd ----
#pragma unroll
        for (int s5 = 0; s5 < 4; s5++) {
            uint32_t a[4] = { ph[2 * s5], ph2[2 * s5], ph[2 * s5 + 1], ph2[2 * s5 + 1] };
#pragma unroll
            for (int nb = 0; nb < 8; nb++) {
                uint32_t bb[4];
                int lg  = lane >> 3;
                int row = s5 * 16 + ((lg & 1) << 3) + (lane & 7);
                int ch  = nb * 2 + (lg >> 1);
                ldsm_x4_t(bb, Vb + (uint32_t)row * 256 + ((ch ^ (row & 7)) * 16));
                mma_f16(o[2 * nb],     a, bb[0], bb[1]);
                mma_f16(o[2 * nb + 1], a, bb[2], bb[3]);
            }
        }
        __syncthreads();
    }

    // ---- finalize ----
    l0 += __shfl_xor_sync(0xffffffffu, l0, 1);
    l0 += __shfl_xor_sync(0xffffffffu, l0, 2);
    l1 += __shfl_xor_sync(0xffffffffu, l1, 1);
    l1 += __shfl_xor_sync(0xffffffffu, l1, 2);
    float inv0 = 1.f / l0, inv1 = 1.f / l1;

    float* Og = O + ((size_t)(b * S_) + q0) * H_ + h * HD_;
    int r0 = wid * 16 + g;
#pragma unroll
    for (int nb = 0; nb < 16; nb++) {
        int cc = nb * 8 + t4 * 2;
        *(float2*)&Og[(size_t)r0 * H_ + cc] =
            make_float2(o[nb][0] * inv0, o[nb][1] * inv0);
        *(float2*)&Og[(size_t)(r0 + 8) * H_ + cc] =
            make_float2(o[nb][2] * inv1, o[nb][3] * inv1);
    }
}

// ---------------------------------------------------------------------------
// kernel_launch
// ---------------------------------------------------------------------------
extern "C" void kernel_launch(void* const* d_in, const int* in_sizes, int n_in,
                              void* d_out, int out_size)
{
    const float* X  = (const float*)d_in[0];
    const float* Wq = (const float*)d_in[1];
    const float* bq = (const float*)d_in[2];
    const float* Wk = (const float*)d_in[3];
    const float* bk = (const float*)d_in[4];
    const float* Wv = (const float*)d_in[5];
    const float* bv = (const float*)d_in[6];
    const float* Wo = (const float*)d_in[7];
    const float* bo = (const float*)d_in[8];
    float* out = (float*)d_out;

    __half *qh, *kh, *vh;
    float* ob;
    __nv_bfloat16 *a3, *w3;
    cudaGetSymbolAddress((void**)&qh, g_Qh);
    cudaGetSymbolAddress((void**)&kh, g_Kh);
    cudaGetSymbolAddress((void**)&vh, g_Vh);
    cudaGetSymbolAddress((void**)&ob, g_O);
    cudaGetSymbolAddress((void**)&a3, g_A3);
    cudaGetSymbolAddress((void**)&w3, g_W3);

    cudaFuncSetAttribute(mma_gemm_kernel,
                         cudaFuncAttributeMaxDynamicSharedMemorySize, GEMM_SMEM);
    cudaFuncSetAttribute(attn_mma_kernel,
                         cudaFuncAttributeMaxDynamicSharedMemorySize, ATTN_SMEM);

    const int splitA_blocks = (M_ * (H_ / 4)) / 256;  // 8192
    const int splitW_blocks = (H_ * (H_ / 4)) / 256;  // 4096
    dim3 ggrid(H_ / 128, M_ / 128);                   // (16, 32)

    // QKV projections (bf16 3-term split) -> fp16 outputs
    split3_kernel<<<splitA_blocks, 256>>>(X, a3, M_, 0);
    split3_kernel<<<splitW_blocks, 256>>>(Wq, w3, H_, 1);
    mma_gemm_kernel<<<ggrid, 256, GEMM_SMEM>>>(a3, w3, bq, nullptr, qh);
    split3_kernel<<<splitW_blocks, 256>>>(Wk, w3, H_, 1);
    mma_gemm_kernel<<<ggrid, 256, GEMM_SMEM>>>(a3, w3, bk, nullptr, kh);
    split3_kernel<<<splitW_blocks, 256>>>(Wv, w3, H_, 1);
    mma_gemm_kernel<<<ggrid, 256, GEMM_SMEM>>>(a3, w3, bv, nullptr, vh);

    // fp16 mma attention -> fp32 g_O
    dim3 agrid(S_ / 128, B_ * NH_);                   // (16, 32)
    attn_mma_kernel<<<agrid, 256, ATTN_SMEM>>>(qh, kh, vh, ob);

    // output projection (fp32 out)
    split3_kernel<<<splitA_blocks, 256>>>(ob, a3, M_, 0);
    split3_kernel<<<splitW_blocks, 256>>>(Wo, w3, H_, 1);
    mma_gemm_kernel<<<ggrid, 256, GEMM_SMEM>>>(a3, w3, bo, out, nullptr);
}

// round 14
// speedup vs baseline: 5.6854x; 1.4451x over previous
#include <cuda_runtime.h>
#include <cuda_fp16.h>
#include <cstdint>

#define B_  2
#define S_  2048
#define H_  2048
#define NH_ 16
#define HD_ 128
#define M_  (B_ * S_)     // 4096 rows
#define H3_ 6144          // packed QKV width
#define K2_ 4096          // [hi | lo] fp16 split columns
#define NT2 (K2_ / 64)    // 64 k-iterations of 64 elems

// ---------------------------------------------------------------------------
// Scratch (__device__ globals: allocation-free rule)
// ---------------------------------------------------------------------------
__device__ __half g_A2  [(size_t)M_ * K2_];    // split activations [hi|lo]
__device__ __half g_Wh  [(size_t)H3_ * H_];    // fp16 weights (QKV rows or Wo)
__device__ __half g_QKVh[(size_t)M_ * H3_];    // packed Q|K|V fp16
__device__ float  g_O   [(size_t)M_ * H_];     // attention output fp32
__device__ float  g_bc  [H3_];                 // concatenated bias

// ---------------------------------------------------------------------------
// Helpers (compute_103-legal PTX: cp.async, ldmatrix, mma.sync)
// ---------------------------------------------------------------------------
__device__ __forceinline__ uint32_t smem_u32(const void* p) {
    uint32_t a;
    asm("{ .reg .u64 t; cvta.to.shared.u64 t, %1; cvt.u32.u64 %0, t; }"
        : "=r"(a) : "l"(p));
    return a;
}
__device__ __forceinline__ void cp16(uint32_t s, const void* g) {
    asm volatile("cp.async.cg.shared.global [%0], [%1], 16;"
                 :: "r"(s), "l"(g) : "memory");
}
#define CP_COMMIT() asm volatile("cp.async.commit_group;" ::: "memory")
#define CP_WAIT(N)  asm volatile("cp.async.wait_group %0;" :: "n"(N) : "memory")

__device__ __forceinline__ void ldsm_x4(uint32_t r[4], uint32_t addr) {
    asm volatile("ldmatrix.sync.aligned.m8n8.x4.shared.b16 {%0,%1,%2,%3}, [%4];"
                 : "=r"(r[0]), "=r"(r[1]), "=r"(r[2]), "=r"(r[3]) : "r"(addr));
}
__device__ __forceinline__ void ldsm_x4_t(uint32_t r[4], uint32_t addr) {
    asm volatile("ldmatrix.sync.aligned.m8n8.x4.trans.shared.b16 {%0,%1,%2,%3}, [%4];"
                 : "=r"(r[0]), "=r"(r[1]), "=r"(r[2]), "=r"(r[3]) : "r"(addr));
}
__device__ __forceinline__ void mma_f16(float d[4], const uint32_t a[4],
                                        uint32_t b0, uint32_t b1) {
    asm volatile(
        "mma.sync.aligned.m16n8k16.row.col.f32.f16.f16.f32 "
        "{%0,%1,%2,%3}, {%4,%5,%6,%7}, {%8,%9}, {%0,%1,%2,%3};"
        : "+f"(d[0]), "+f"(d[1]), "+f"(d[2]), "+f"(d[3])
        : "r"(a[0]), "r"(a[1]), "r"(a[2]), "r"(a[3]), "r"(b0), "r"(b1));
}
__device__ __forceinline__ uint32_t pack_h2(float lo, float hi) {
    uint32_t u;
    asm("cvt.rn.f16x2.f32 %0, %1, %2;" : "=r"(u) : "f"(hi), "f"(lo));
    return u;
}
// FFMA-only exp2 (no MUFU): magic-number round, deg-4 Taylor on [-0.5,0.5],
// exponent splice. Rel err ~4e-5.
__device__ __forceinline__ float fexp2(float t) {
    t = fmaxf(t, -120.f);
    float z = t + 12582912.f;
    int   k = __float_as_int(z) - 0x4B400000;
    float r = t - (z - 12582912.f);
    float p = 1.f + r * (0.69314718f + r * (0.24022651f +
                   r * (0.05550411f + r * 0.00961813f)));
    return __int_as_float(__float_as_int(p) + (k << 23));
}

// ---------------------------------------------------------------------------
// splitA2: X[rows,2048] fp32 -> Y[rows,4096] fp16, [hi | residual].
// (hi + lo) == x to ~2^-23, so GEMM vs fp16 weights is exact in X.
// ---------------------------------------------------------------------------
__global__ void __launch_bounds__(256)
splitA2_kernel(const float* __restrict__ X, __half* __restrict__ Y, int nrows)
{
    int t   = blockIdx.x * 256 + threadIdx.x;
    int row = t >> 9;                // 512 float4 per row
    int k4  = t & 511;
    if (row >= nrows) return;
    float4 x = *(const float4*)(X + (size_t)row * H_ + k4 * 4);
    __half h0 = __float2half_rn(x.x), h1 = __float2half_rn(x.y);
    __half h2 = __float2half_rn(x.z), h3 = __float2half_rn(x.w);
    __half l0 = __float2half_rn(x.x - __half2float(h0));
    __half l1 = __float2half_rn(x.y - __half2float(h1));
    __half l2 = __float2half_rn(x.z - __half2float(h2));
    __half l3 = __float2half_rn(x.w - __half2float(h3));
    __half* out = Y + (size_t)row * K2_ + k4 * 4;
    *(__half2*)(out + 0)        = __halves2half2(h0, h1);
    *(__half2*)(out + 2)        = __halves2half2(h2, h3);
    *(__half2*)(out + H_)       = __halves2half2(l0, l1);
    *(__half2*)(out + H_ + 2)   = __halves2half2(l2, l3);
}

// splitWh: W[2048,2048] fp32 -> fp16 (plain convert), at row offset in g_Wh.
__global__ void __launch_bounds__(256)
splitWh_kernel(const float* __restrict__ W, __half* __restrict__ Y)
{
    int t = blockIdx.x * 256 + threadIdx.x;        // over 2048*512 float4
    float4 x = *(const float4*)(W + (size_t)t * 4);
    __half2 a = __floats2half2_rn(x.x, x.y);
    __half2 b = __floats2half2_rn(x.z, x.w);
    *(__half2*)(Y + (size_t)t * 4)     = a;
    *(__half2*)(Y + (size_t)t * 4 + 2) = b;
}

__global__ void biascat_kernel(const float* __restrict__ bq,
                               const float* __restrict__ bk,
                               const float* __restrict__ bv,
                               float* __restrict__ bc)
{
    int i = blockIdx.x * 256 + threadIdx.x;        // 6144
    float v = (i < 2048) ? bq[i] : (i < 4096 ? bk[i - 2048] : bv[i - 4096]);
    bc[i] = v;
}

// ---------------------------------------------------------------------------
// fp16 mma GEMM: C[M,N] = A2[M,4096] @ Wh[N,2048]^T (+bias), B col = k mod 2048
// so result = (Xh+Xl)@Wh^T = X@Wh^T. 128x128 CTA tile, 8 warps, BK=64,
// cp.async double buffer, 2 CTAs/SM.
// ---------------------------------------------------------------------------
#define GEMM_SMEM 65536

__global__ void __launch_bounds__(256, 2)
gemm2_kernel(const __half* __restrict__ A2, const __half* __restrict__ Wh,
             const float* __restrict__ bias,
             __half* __restrict__ outH, float* __restrict__ outF, int ldc)
{
    extern __shared__ __align__(128) char smem[];
    const uint32_t sb   = smem_u32(smem);
    const int tid    = threadIdx.x;
    const int wid    = tid >> 5;
    const int lane   = tid & 31;
    const int warp_m = wid >> 2;
    const int warp_n = wid & 3;
    const int m0 = blockIdx.y * 128;
    const int n0 = blockIdx.x * 128;

    const __half* Ag = A2 + (size_t)m0 * K2_;
    const __half* Bg = Wh + (size_t)n0 * H_;

    float d[4][4][4];
#pragma unroll
    for (int i = 0; i < 4; i++)
#pragma unroll
        for (int j = 0; j < 4; j++)
#pragma unroll
            for (int k = 0; k < 4; k++) d[i][j][k] = 0.f;

    auto load = [&](int it, int buf) {
        uint32_t base = sb + buf * 32768;
        int kA = it * 64;
        int kB = (it & 31) * 64;       // Wh has only 2048 cols; reuse for lo half
#pragma unroll
        for (int l = 0; l < 4; l++) {
            int idx = tid + l * 256;
            int r   = idx >> 3;
            int c   = idx & 7;
            uint32_t sw = (uint32_t)r * 128 + ((c ^ (r & 7)) * 16);
            cp16(base + sw,          Ag + (size_t)r * K2_ + kA + c * 8);
            cp16(base + 16384 + sw,  Bg + (size_t)r * H_  + kB + c * 8);
        }
        CP_COMMIT();
    };

    load(0, 0);

    for (int it = 0; it < NT2; it++) {
        const int buf = it & 1;
        if (it + 1 < NT2) { load(it + 1, buf ^ 1); CP_WAIT(1); }
        else              { CP_WAIT(0); }
        __syncthreads();

        const uint32_t Ab = sb + buf * 32768;
        const uint32_t Bb = Ab + 16384;

#pragma unroll
        for (int ks = 0; ks < 4; ks++) {
            uint32_t a[4][4];
#pragma unroll
            for (int mi = 0; mi < 4; mi++) {
                int row = warp_m * 64 + mi * 16 + (lane & 15);
                int ch  = 2 * ks + (lane >> 4);
                ldsm_x4(a[mi], Ab + (uint32_t)row * 128 + ((ch ^ (row & 7)) * 16));
            }
            uint32_t b[2][4];
#pragma unroll
            for (int j2 = 0; j2 < 2; j2++) {
                int row = warp_n * 32 + j2 * 16 + (lane & 7) + ((lane >> 4) << 3);
                int ch  = 2 * ks + ((lane >> 3) & 1);
                ldsm_x4(b[j2], Bb + (uint32_t)row * 128 + ((ch ^ (row & 7)) * 16));
            }
#pragma unroll
            for (int mi = 0; mi < 4; mi++)
#pragma unroll
                for (int j2 = 0; j2 < 2; j2++) {
                    mma_f16(d[mi][2 * j2],     a[mi], b[j2][0], b[j2][1]);
                    mma_f16(d[mi][2 * j2 + 1], a[mi], b[j2][2], b[j2][3]);
                }
        }
        __syncthreads();
    }

#pragma unroll
    for (int mi = 0; mi < 4; mi++) {
        int r0 = m0 + warp_m * 64 + mi * 16 + (lane >> 2);
#pragma unroll
        for (int ni = 0; ni < 4; ni++) {
            int cc = n0 + warp_n * 32 + ni * 8 + (lane & 3) * 2;
            float2 bv = *(const float2*)&bias[cc];
            float v00 = d[mi][ni][0] + bv.x, v01 = d[mi][ni][1] + bv.y;
            float v10 = d[mi][ni][2] + bv.x, v11 = d[mi][ni][3] + bv.y;
            if (outH) {
                *(__half2*)&outH[(size_t)r0 * ldc + cc] =
                    __floats2half2_rn(v00, v01);
                *(__half2*)&outH[(size_t)(r0 + 8) * ldc + cc] =
                    __floats2half2_rn(v10, v11);
            } else {
                *(float2*)&outF[(size_t)r0 * ldc + cc]       = make_float2(v00, v01);
                *(float2*)&outF[(size_t)(r0 + 8) * ldc + cc] = make_float2(v10, v11);
            }
        }
    }
}

// ---------------------------------------------------------------------------
// FA2-style fp16 mma attention over packed QKV [M x 6144].
// CTA: 128 q-rows x one (b,h). 8 warps x 16 rows. Q resident; K/V 64-row
// double-buffered. exp via FFMA-only fexp2.
// ---------------------------------------------------------------------------
#define ATTN_SMEM 98304

__global__ void __launch_bounds__(256)
attn_mma_kernel(const __half* __restrict__ QKV, float* __restrict__ O)
{
    extern __shared__ __align__(128) char smem[];
    const uint32_t sb  = smem_u32(smem);
    const uint32_t Qs  = sb;            // 128 rows x 256 B
    const uint32_t KVs = sb + 32768;    // 2 x (K 16KB + V 16KB)

    const int tid  = threadIdx.x;
    const int wid  = tid >> 5;
    const int lane = tid & 31;
    const int g    = lane >> 2;
    const int t4   = lane & 3;
    const int bh = blockIdx.y;
    const int b  = bh >> 4;
    const int h  = bh & 15;
    const int q0 = blockIdx.x * 128;

    const __half* Qg = QKV + ((size_t)(b * S_) + q0) * H3_ + h * HD_;
    const __half* Kg = QKV + (size_t)(b * S_) * H3_ + 2048 + h * HD_;
    const __half* Vg = QKV + (size_t)(b * S_) * H3_ + 4096 + h * HD_;

#pragma unroll
    for (int l = 0; l < 8; l++) {
        int idx = tid + l * 256;
        int r = idx >> 4, c = idx & 15;
        cp16(Qs + r * 256 + ((c ^ (r & 7)) * 16), Qg + (size_t)r * H3_ + c * 8);
    }

    auto loadKV = [&](int kt, int buf) {
        uint32_t base = KVs + buf * 32768;
#pragma unroll
        for (int l = 0; l < 4; l++) {
            int idx = tid + l * 256;
            int r = idx >> 4, c = idx & 15;
            uint32_t sw = (uint32_t)r * 256 + ((c ^ (r & 7)) * 16);
            cp16(base + sw,         Kg + (size_t)(kt * 64 + r) * H3_ + c * 8);
            cp16(base + 16384 + sw, Vg + (size_t)(kt * 64 + r) * H3_ + c * 8);
        }
        CP_COMMIT();
    };
    loadKV(0, 0);

    float o[16][4];
#pragma unroll
    for (int n = 0; n < 16; n++)
#pragma unroll
        for (int k = 0; k < 4; k++) o[n][k] = 0.f;
    float m0 = -1e30f, m1 = -1e30f, l0 = 0.f, l1 = 0.f;
    const float cexp = 0.08838834764831845f * 1.4426950408889634f;

    const int NIT = S_ / 64;
    for (int it = 0; it < NIT; it++) {
        const int buf = it & 1;
        if (it + 1 < NIT) { loadKV(it + 1, buf ^ 1); CP_WAIT(1); }
        else              { CP_WAIT(0); }
        __syncthreads();
        const uint32_t Kb = KVs + buf * 32768;
        const uint32_t Vb = Kb + 16384;

        float s[8][4];
#pragma unroll
        for (int j = 0; j < 8; j++)
#pragma unroll
            for (int k = 0; k < 4; k++) s[j][k] = 0.f;

#pragma unroll
        for (int ks = 0; ks < 8; ks++) {
            uint32_t a[4];
            {
                int row = wid * 16 + (lane & 15);
                int ch  = 2 * ks + (lane >> 4);
                ldsm_x4(a, Qs + (uint32_t)row * 256 + ((ch ^ (row & 7)) * 16));
            }
#pragma unroll
            for (int j2 = 0; j2 < 4; j2++) {
                uint32_t bb[4];
                int row = j2 * 16 + (lane & 7) + ((lane >> 4) << 3);
                int ch  = 2 * ks + ((lane >> 3) & 1);
                ldsm_x4(bb, Kb + (uint32_t)row * 256 + ((ch ^ (row & 7)) * 16));
                mma_f16(s[2 * j2],     a, bb[0], bb[1]);
                mma_f16(s[2 * j2 + 1], a, bb[2], bb[3]);
            }
        }

        float mx0 = s[0][0], mx1 = s[0][2];
#pragma unroll
        for (int j = 0; j < 8; j++) {
            mx0 = fmaxf(mx0, fmaxf(s[j][0], s[j][1]));
            mx1 = fmaxf(mx1, fmaxf(s[j][2], s[j][3]));
        }
        mx0 = fmaxf(mx0, __shfl_xor_sync(0xffffffffu, mx0, 1));
        mx0 = fmaxf(mx0, __shfl_xor_sync(0xffffffffu, mx0, 2));
        mx1 = fmaxf(mx1, __shfl_xor_sync(0xffffffffu, mx1, 1));
        mx1 = fmaxf(mx1, __shfl_xor_sync(0xffffffffu, mx1, 2));
        float nm0 = fmaxf(m0, mx0), nm1 = fmaxf(m1, mx1);
        float al0 = fexp2((m0 - nm0) * cexp);
        float al1 = fexp2((m1 - nm1) * cexp);
        m0 = nm0; m1 = nm1;

        float rs0 = 0.f, rs1 = 0.f;
        uint32_t ph[8], ph2[8];
#pragma unroll
        for (int j = 0; j < 8; j++) {
            float p0 = fexp2((s[j][0] - nm0) * cexp);
            float p1 = fexp2((s[j][1] - nm0) * cexp);
            float p2 = fexp2((s[j][2] - nm1) * cexp);
            float p3 = fexp2((s[j][3] - nm1) * cexp);
            rs0 += p0 + p1; rs1 += p2 + p3;
            ph[j]  = pack_h2(p0, p1);
            ph2[j] = pack_h2(p2, p3);
        }
        l0 = l0 * al0 + rs0;
        l1 = l1 * al1 + rs1;
#pragma unroll
        for (int n = 0; n < 16; n++) {
            o[n][0] *= al0; o[n][1] *= al0;
            o[n][2] *= al1; o[n][3] *= al1;
        }

#pragma unroll
        for (int s5 = 0; s5 < 4; s5++) {
            uint32_t a[4] = { ph[2 * s5], ph2[2 * s5], ph[2 * s5 + 1], ph2[2 * s5 + 1] };
#pragma unroll
            for (int nb = 0; nb < 8; nb++) {
                uint32_t bb[4];
                int lg  = lane >> 3;
                int row = s5 * 16 + ((lg & 1) << 3) + (lane & 7);
                int ch  = nb * 2 + (lg >> 1);
                ldsm_x4_t(bb, Vb + (uint32_t)row * 256 + ((ch ^ (row & 7)) * 16));
                mma_f16(o[2 * nb],     a, bb[0], bb[1]);
                mma_f16(o[2 * nb + 1], a, bb[2], bb[3]);
            }
        }
        __syncthreads();
    }

    l0 += __shfl_xor_sync(0xffffffffu, l0, 1);
    l0 += __shfl_xor_sync(0xffffffffu, l0, 2);
    l1 += __shfl_xor_sync(0xffffffffu, l1, 1);
    l1 += __shfl_xor_sync(0xffffffffu, l1, 2);
    float inv0 = 1.f / l0, inv1 = 1.f / l1;

    float* Og = O + ((size_t)(b * S_) + q0) * H_ + h * HD_;
    int r0 = wid * 16 + g;
#pragma unroll
    for (int nb = 0; nb < 16; nb++) {
        int cc = nb * 8 + t4 * 2;
        *(float2*)&Og[(size_t)r0 * H_ + cc] =
            make_float2(o[nb][0] * inv0, o[nb][1] * inv0);
        *(float2*)&Og[(size_t)(r0 + 8) * H_ + cc] =
            make_float2(o[nb][2] * inv1, o[nb][3] * inv1);
    }
}

// ---------------------------------------------------------------------------
// kernel_launch
// ---------------------------------------------------------------------------
extern "C" void kernel_launch(void* const* d_in, const int* in_sizes, int n_in,
                              void* d_out, int out_size)
{
    const float* X  = (const float*)d_in[0];
    const float* Wq = (const float*)d_in[1];
    const float* bq = (const float*)d_in[2];
    const float* Wk = (const float*)d_in[3];
    const float* bk = (const float*)d_in[4];
    const float* Wv = (const float*)d_in[5];
    const float* bv = (const float*)d_in[6];
    const float* Wo = (const float*)d_in[7];
    const float* bo = (const float*)d_in[8];
    float* out = (float*)d_out;

    __half *a2, *wh, *qkvh;
    float *ob, *bc;
    cudaGetSymbolAddress((void**)&a2,   g_A2);
    cudaGetSymbolAddress((void**)&wh,   g_Wh);
    cudaGetSymbolAddress((void**)&qkvh, g_QKVh);
    cudaGetSymbolAddress((void**)&ob,   g_O);
    cudaGetSymbolAddress((void**)&bc,   g_bc);

    cudaFuncSetAttribute(gemm2_kernel,
                         cudaFuncAttributeMaxDynamicSharedMemorySize, GEMM_SMEM);
    cudaFuncSetAttribute(attn_mma_kernel,
                         cudaFuncAttributeMaxDynamicSharedMemorySize, ATTN_SMEM);

    const int splitA_blocks = M_ * 2;                  // M*512/256
    const int splitW_blocks = (H_ * H_ / 4) / 256;     // 4096

    // --- stage 1: split X, convert QKV weights, concat bias ---
    splitA2_kernel<<<splitA_blocks, 256>>>(X, a2, M_);
    splitWh_kernel<<<splitW_blocks, 256>>>(Wq, wh);
    splitWh_kernel<<<splitW_blocks, 256>>>(Wk, wh + (size_t)H_ * H_);
    splitWh_kernel<<<splitW_blocks, 256>>>(Wv, wh + (size_t)2 * H_ * H_);
    biascat_kernel<<<H3_ / 256, 256>>>(bq, bk, bv, bc);

    // --- stage 2: fused QKV projection (N=6144) -> packed fp16 QKV ---
    dim3 qkv_grid(H3_ / 128, M_ / 128);                // (48, 32)
    gemm2_kernel<<<qkv_grid, 256, GEMM_SMEM>>>(a2, wh, bc, qkvh, nullptr, H3_);

    // --- stage 3: attention ---
    dim3 agrid(S_ / 128, B_ * NH_);                    // (16, 32)
    attn_mma_kernel<<<agrid, 256, ATTN_SMEM>>>(qkvh, ob);

    // --- stage 4: output projection ---
    splitA2_kernel<<<splitA_blocks, 256>>>(ob, a2, M_);
    splitWh_kernel<<<splitW_blocks, 256>>>(Wo, wh);
    dim3 ogrid(H_ / 128, M_ / 128);                    // (16, 32)
    gemm2_kernel<<<ogrid, 256, GEMM_SMEM>>>(a2, wh, bo, nullptr, out, H_);
}

// round 15
// speedup vs baseline: 8.1233x; 1.4288x over previous
#include <cuda_runtime.h>
#include <cuda_fp16.h>
#include <cstdint>

#define B_  2
#define S_  2048
#define H_  2048
#define NH_ 16
#define HD_ 128
#define M_  (B_ * S_)     // 4096 rows
#define H3_ 6144          // packed QKV width
#define NTK (H_ / 64)     // 32 k-iterations of 64 elems

// ---------------------------------------------------------------------------
// Scratch (__device__ globals: allocation-free rule)
// ---------------------------------------------------------------------------
__device__ __half g_Ah  [(size_t)M_ * H_];       // fp16 activations (X, then attn out)
__device__ __half g_Wh  [(size_t)4 * H_ * H_];   // fp16 weights: Wq|Wk|Wv|Wo
__device__ __half g_QKVh[(size_t)M_ * H3_];      // packed Q|K|V fp16
__device__ float  g_bc  [H3_];                   // concatenated QKV bias

// ---------------------------------------------------------------------------
// Helpers (compute_103-legal PTX: cp.async, ldmatrix, mma.sync)
// ---------------------------------------------------------------------------
__device__ __forceinline__ uint32_t smem_u32(const void* p) {
    uint32_t a;
    asm("{ .reg .u64 t; cvta.to.shared.u64 t, %1; cvt.u32.u64 %0, t; }"
        : "=r"(a) : "l"(p));
    return a;
}
__device__ __forceinline__ void cp16(uint32_t s, const void* g) {
    asm volatile("cp.async.cg.shared.global [%0], [%1], 16;"
                 :: "r"(s), "l"(g) : "memory");
}
#define CP_COMMIT() asm volatile("cp.async.commit_group;" ::: "memory")
#define CP_WAIT(N)  asm volatile("cp.async.wait_group %0;" :: "n"(N) : "memory")

__device__ __forceinline__ void ldsm_x4(uint32_t r[4], uint32_t addr) {
    asm volatile("ldmatrix.sync.aligned.m8n8.x4.shared.b16 {%0,%1,%2,%3}, [%4];"
                 : "=r"(r[0]), "=r"(r[1]), "=r"(r[2]), "=r"(r[3]) : "r"(addr));
}
__device__ __forceinline__ void ldsm_x4_t(uint32_t r[4], uint32_t addr) {
    asm volatile("ldmatrix.sync.aligned.m8n8.x4.trans.shared.b16 {%0,%1,%2,%3}, [%4];"
                 : "=r"(r[0]), "=r"(r[1]), "=r"(r[2]), "=r"(r[3]) : "r"(addr));
}
__device__ __forceinline__ void mma_f16(float d[4], const uint32_t a[4],
                                        uint32_t b0, uint32_t b1) {
    asm volatile(
        "mma.sync.aligned.m16n8k16.row.col.f32.f16.f16.f32 "
        "{%0,%1,%2,%3}, {%4,%5,%6,%7}, {%8,%9}, {%0,%1,%2,%3};"
        : "+f"(d[0]), "+f"(d[1]), "+f"(d[2]), "+f"(d[3])
        : "r"(a[0]), "r"(a[1]), "r"(a[2]), "r"(a[3]), "r"(b0), "r"(b1));
}
__device__ __forceinline__ uint32_t pack_h2(float lo, float hi) {
    uint32_t u;
    asm("cvt.rn.f16x2.f32 %0, %1, %2;" : "=r"(u) : "f"(hi), "f"(lo));
    return u;
}
// FFMA-only exp2 (no MUFU): magic-number round, deg-4 Taylor on [-0.5,0.5],
// exponent splice. Rel err ~4e-5.
__device__ __forceinline__ float fexp2(float t) {
    t = fmaxf(t, -120.f);
    float z = t + 12582912.f;
    int   k = __float_as_int(z) - 0x4B400000;
    float r = t - (z - 12582912.f);
    float p = 1.f + r * (0.69314718f + r * (0.24022651f +
                   r * (0.05550411f + r * 0.00961813f)));
    return __int_as_float(__float_as_int(p) + (k << 23));
}

// ---------------------------------------------------------------------------
// Generic fp32 -> fp16 convert (vectorized float4 -> half2 x2).
// ---------------------------------------------------------------------------
__global__ void __launch_bounds__(256)
cvt_f2h_kernel(const float* __restrict__ X, __half* __restrict__ Y)
{
    int t = blockIdx.x * 256 + threadIdx.x;
    float4 x = *(const float4*)(X + (size_t)t * 4);
    *(__half2*)(Y + (size_t)t * 4)     = __floats2half2_rn(x.x, x.y);
    *(__half2*)(Y + (size_t)t * 4 + 2) = __floats2half2_rn(x.z, x.w);
}

__global__ void biascat_kernel(const float* __restrict__ bq,
                               const float* __restrict__ bk,
                               const float* __restrict__ bv,
                               float* __restrict__ bc)
{
    int i = blockIdx.x * 256 + threadIdx.x;        // 6144
    float v = (i < 2048) ? bq[i] : (i < 4096 ? bk[i - 2048] : bv[i - 4096]);
    bc[i] = v;
}

// ---------------------------------------------------------------------------
// fp16 mma GEMM: C[M,N] = A[M,2048] @ Wh[N,2048]^T + bias (fp32 accumulate).
// 128x128 CTA tile, 8 warps, BK=64, cp.async double buffer, 2 CTAs/SM.
// ---------------------------------------------------------------------------
#define GEMM_SMEM 65536

__global__ void __launch_bounds__(256, 2)
gemm2_kernel(const __half* __restrict__ A, const __half* __restrict__ Wh,
             const float* __restrict__ bias,
             __half* __restrict__ outH, float* __restrict__ outF, int ldc)
{
    extern __shared__ __align__(128) char smem[];
    const uint32_t sb   = smem_u32(smem);
    const int tid    = threadIdx.x;
    const int wid    = tid >> 5;
    const int lane   = tid & 31;
    const int warp_m = wid >> 2;
    const int warp_n = wid & 3;
    const int m0 = blockIdx.y * 128;
    const int n0 = blockIdx.x * 128;

    const __half* Ag = A  + (size_t)m0 * H_;
    const __half* Bg = Wh + (size_t)n0 * H_;

    float d[4][4][4];
#pragma unroll
    for (int i = 0; i < 4; i++)
#pragma unroll
        for (int j = 0; j < 4; j++)
#pragma unroll
            for (int k = 0; k < 4; k++) d[i][j][k] = 0.f;

    auto load = [&](int it, int buf) {
        uint32_t base = sb + buf * 32768;
        int kk = it * 64;
#pragma unroll
        for (int l = 0; l < 4; l++) {
            int idx = tid + l * 256;
            int r   = idx >> 3;
            int c   = idx & 7;
            uint32_t sw = (uint32_t)r * 128 + ((c ^ (r & 7)) * 16);
            cp16(base + sw,          Ag + (size_t)r * H_ + kk + c * 8);
            cp16(base + 16384 + sw,  Bg + (size_t)r * H_ + kk + c * 8);
        }
        CP_COMMIT();
    };

    load(0, 0);

    for (int it = 0; it < NTK; it++) {
        const int buf = it & 1;
        if (it + 1 < NTK) { load(it + 1, buf ^ 1); CP_WAIT(1); }
        else              { CP_WAIT(0); }
        __syncthreads();

        const uint32_t Ab = sb + buf * 32768;
        const uint32_t Bb = Ab + 16384;

#pragma unroll
        for (int ks = 0; ks < 4; ks++) {
            uint32_t a[4][4];
#pragma unroll
            for (int mi = 0; mi < 4; mi++) {
                int row = warp_m * 64 + mi * 16 + (lane & 15);
                int ch  = 2 * ks + (lane >> 4);
                ldsm_x4(a[mi], Ab + (uint32_t)row * 128 + ((ch ^ (row & 7)) * 16));
            }
            uint32_t b[2][4];
#pragma unroll
            for (int j2 = 0; j2 < 2; j2++) {
                int row = warp_n * 32 + j2 * 16 + (lane & 7) + ((lane >> 4) << 3);
                int ch  = 2 * ks + ((lane >> 3) & 1);
                ldsm_x4(b[j2], Bb + (uint32_t)row * 128 + ((ch ^ (row & 7)) * 16));
            }
#pragma unroll
            for (int mi = 0; mi < 4; mi++)
#pragma unroll
                for (int j2 = 0; j2 < 2; j2++) {
                    mma_f16(d[mi][2 * j2],     a[mi], b[j2][0], b[j2][1]);
                    mma_f16(d[mi][2 * j2 + 1], a[mi], b[j2][2], b[j2][3]);
                }
        }
        __syncthreads();
    }

#pragma unroll
    for (int mi = 0; mi < 4; mi++) {
        int r0 = m0 + warp_m * 64 + mi * 16 + (lane >> 2);
#pragma unroll
        for (int ni = 0; ni < 4; ni++) {
            int cc = n0 + warp_n * 32 + ni * 8 + (lane & 3) * 2;
            float2 bv = *(const float2*)&bias[cc];
            float v00 = d[mi][ni][0] + bv.x, v01 = d[mi][ni][1] + bv.y;
            float v10 = d[mi][ni][2] + bv.x, v11 = d[mi][ni][3] + bv.y;
            if (outH) {
                *(__half2*)&outH[(size_t)r0 * ldc + cc] =
                    __floats2half2_rn(v00, v01);
                *(__half2*)&outH[(size_t)(r0 + 8) * ldc + cc] =
                    __floats2half2_rn(v10, v11);
            } else {
                *(float2*)&outF[(size_t)r0 * ldc + cc]       = make_float2(v00, v01);
                *(float2*)&outF[(size_t)(r0 + 8) * ldc + cc] = make_float2(v10, v11);
            }
        }
    }
}

// ---------------------------------------------------------------------------
// FA2-style fp16 mma attention over packed QKV [M x 6144].
// CTA: 128 q-rows x one (b,h). 8 warps x 16 rows. Q resident; K/V 64-row
// double-buffered. exp via FFMA-only fexp2. Output written as fp16 directly
// into the stage-4 activation buffer (no fp32 round-trip).
// ---------------------------------------------------------------------------
#define ATTN_SMEM 98304

__global__ void __launch_bounds__(256)
attn_mma_kernel(const __half* __restrict__ QKV, __half* __restrict__ AOut)
{
    extern __shared__ __align__(128) char smem[];
    const uint32_t sb  = smem_u32(smem);
    const uint32_t Qs  = sb;            // 128 rows x 256 B
    const uint32_t KVs = sb + 32768;    // 2 x (K 16KB + V 16KB)

    const int tid  = threadIdx.x;
    const int wid  = tid >> 5;
    const int lane = tid & 31;
    const int g    = lane >> 2;
    const int t4   = lane & 3;
    const int bh = blockIdx.y;
    const int b  = bh >> 4;
    const int h  = bh & 15;
    const int q0 = blockIdx.x * 128;

    const __half* Qg = QKV + ((size_t)(b * S_) + q0) * H3_ + h * HD_;
    const __half* Kg = QKV + (size_t)(b * S_) * H3_ + 2048 + h * HD_;
    const __half* Vg = QKV + (size_t)(b * S_) * H3_ + 4096 + h * HD_;

#pragma unroll
    for (int l = 0; l < 8; l++) {
        int idx = tid + l * 256;
        int r = idx >> 4, c = idx & 15;
        cp16(Qs + r * 256 + ((c ^ (r & 7)) * 16), Qg + (size_t)r * H3_ + c * 8);
    }

    auto loadKV = [&](int kt, int buf) {
        uint32_t base = KVs + buf * 32768;
#pragma unroll
        for (int l = 0; l < 4; l++) {
            int idx = tid + l * 256;
            int r = idx >> 4, c = idx & 15;
            uint32_t sw = (uint32_t)r * 256 + ((c ^ (r & 7)) * 16);
            cp16(base + sw,         Kg + (size_t)(kt * 64 + r) * H3_ + c * 8);
            cp16(base + 16384 + sw, Vg + (size_t)(kt * 64 + r) * H3_ + c * 8);
        }
        CP_COMMIT();
    };
    loadKV(0, 0);

    float o[16][4];
#pragma unroll
    for (int n = 0; n < 16; n++)
#pragma unroll
        for (int k = 0; k < 4; k++) o[n][k] = 0.f;
    float m0 = -1e30f, m1 = -1e30f, l0 = 0.f, l1 = 0.f;
    const float cexp = 0.08838834764831845f * 1.4426950408889634f;

    const int NIT = S_ / 64;
    for (int it = 0; it < NIT; it++) {
        const int buf = it & 1;
        if (it + 1 < NIT) { loadKV(it + 1, buf ^ 1); CP_WAIT(1); }
        else              { CP_WAIT(0); }
        __syncthreads();
        const uint32_t Kb = KVs + buf * 32768;
        const uint32_t Vb = Kb + 16384;

        float s[8][4];
#pragma unroll
        for (int j = 0; j < 8; j++)
#pragma unroll
            for (int k = 0; k < 4; k++) s[j][k] = 0.f;

#pragma unroll
        for (int ks = 0; ks < 8; ks++) {
            uint32_t a[4];
            {
                int row = wid * 16 + (lane & 15);
                int ch  = 2 * ks + (lane >> 4);
                ldsm_x4(a, Qs + (uint32_t)row * 256 + ((ch ^ (row & 7)) * 16));
            }
#pragma unroll
            for (int j2 = 0; j2 < 4; j2++) {
                uint32_t bb[4];
                int row = j2 * 16 + (lane & 7) + ((lane >> 4) << 3);
                int ch  = 2 * ks + ((lane >> 3) & 1);
                ldsm_x4(bb, Kb + (uint32_t)row * 256 + ((ch ^ (row & 7)) * 16));
                mma_f16(s[2 * j2],     a, bb[0], bb[1]);
                mma_f16(s[2 * j2 + 1], a, bb[2], bb[3]);
            }
        }

        float mx0 = s[0][0], mx1 = s[0][2];
#pragma unroll
        for (int j = 0; j < 8; j++) {
            mx0 = fmaxf(mx0, fmaxf(s[j][0], s[j][1]));
            mx1 = fmaxf(mx1, fmaxf(s[j][2], s[j][3]));
        }
        mx0 = fmaxf(mx0, __shfl_xor_sync(0xffffffffu, mx0, 1));
        mx0 = fmaxf(mx0, __shfl_xor_sync(0xffffffffu, mx0, 2));
        mx1 = fmaxf(mx1, __shfl_xor_sync(0xffffffffu, mx1, 1));
        mx1 = fmaxf(mx1, __shfl_xor_sync(0xffffffffu, mx1, 2));
        float nm0 = fmaxf(m0, mx0), nm1 = fmaxf(m1, mx1);
        float al0 = fexp2((m0 - nm0) * cexp);
        float al1 = fexp2((m1 - nm1) * cexp);
        m0 = nm0; m1 = nm1;

        float rs0 = 0.f, rs1 = 0.f;
        uint32_t ph[8], ph2[8];
#pragma unroll
        for (int j = 0; j < 8; j++) {
            float p0 = fexp2((s[j][0] - nm0) * cexp);
            float p1 = fexp2((s[j][1] - nm0) * cexp);
            float p2 = fexp2((s[j][2] - nm1) * cexp);
            float p3 = fexp2((s[j][3] - nm1) * cexp);
            rs0 += p0 + p1; rs1 += p2 + p3;
            ph[j]  = pack_h2(p0, p1);
            ph2[j] = pack_h2(p2, p3);
        }
        l0 = l0 * al0 + rs0;
        l1 = l1 * al1 + rs1;
#pragma unroll
        for (int n = 0; n < 16; n++) {
            o[n][0] *= al0; o[n][1] *= al0;
            o[n][2] *= al1; o[n][3] *= al1;
        }

#pragma unroll
        for (int s5 = 0; s5 < 4; s5++) {
            uint32_t a[4] = { ph[2 * s5], ph2[2 * s5], ph[2 * s5 + 1], ph2[2 * s5 + 1] };
#pragma unroll
            for (int nb = 0; nb < 8; nb++) {
                uint32_t bb[4];
                int lg  = lane >> 3;
                int row = s5 * 16 + ((lg & 1) << 3) + (lane & 7);
                int ch  = nb * 2 + (lg >> 1);
                ldsm_x4_t(bb, Vb + (uint32_t)row * 256 + ((ch ^ (row & 7)) * 16));
                mma_f16(o[2 * nb],     a, bb[0], bb[1]);
                mma_f16(o[2 * nb + 1], a, bb[2], bb[3]);
            }
        }
        __syncthreads();
    }

    l0 += __shfl_xor_sync(0xffffffffu, l0, 1);
    l0 += __shfl_xor_sync(0xffffffffu, l0, 2);
    l1 += __shfl_xor_sync(0xffffffffu, l1, 1);
    l1 += __shfl_xor_sync(0xffffffffu, l1, 2);
    float inv0 = 1.f / l0, inv1 = 1.f / l1;

    __half* Og = AOut + ((size_t)(b * S_) + q0) * H_ + h * HD_;
    int r0 = wid * 16 + g;
#pragma unroll
    for (int nb = 0; nb < 16; nb++) {
        int cc = nb * 8 + t4 * 2;
        *(__half2*)&Og[(size_t)r0 * H_ + cc] =
            __floats2half2_rn(o[nb][0] * inv0, o[nb][1] * inv0);
        *(__half2*)&Og[(size_t)(r0 + 8) * H_ + cc] =
            __floats2half2_rn(o[nb][2] * inv1, o[nb][3] * inv1);
    }
}

// ---------------------------------------------------------------------------
// kernel_launch
// ---------------------------------------------------------------------------
extern "C" void kernel_launch(void* const* d_in, const int* in_sizes, int n_in,
                              void* d_out, int out_size)
{
    const float* X  = (const float*)d_in[0];
    const float* Wq = (const float*)d_in[1];
    const float* bq = (const float*)d_in[2];
    const float* Wk = (const float*)d_in[3];
    const float* bk = (const float*)d_in[4];
    const float* Wv = (const float*)d_in[5];
    const float* bv = (const float*)d_in[6];
    const float* Wo = (const float*)d_in[7];
    const float* bo = (const float*)d_in[8];
    float* out = (float*)d_out;

    __half *ah, *wh, *qkvh;
    float *bc;
    cudaGetSymbolAddress((void**)&ah,   g_Ah);
    cudaGetSymbolAddress((void**)&wh,   g_Wh);
    cudaGetSymbolAddress((void**)&qkvh, g_QKVh);
    cudaGetSymbolAddress((void**)&bc,   g_bc);

    cudaFuncSetAttribute(gemm2_kernel,
                         cudaFuncAttributeMaxDynamicSharedMemorySize, GEMM_SMEM);
    cudaFuncSetAttribute(attn_mma_kernel,
                         cudaFuncAttributeMaxDynamicSharedMemorySize, ATTN_SMEM);

    const int cvtX_blocks = (M_ * H_ / 4) / 256;   // 8192
    const int cvtW_blocks = (H_ * H_ / 4) / 256;   // 4096

    // --- stage 1: convert X and all weights to fp16, concat QKV bias ---
    cvt_f2h_kernel<<<cvtX_blocks, 256>>>(X, ah);
    cvt_f2h_kernel<<<cvtW_blocks, 256>>>(Wq, wh);
    cvt_f2h_kernel<<<cvtW_blocks, 256>>>(Wk, wh + (size_t)H_ * H_);
    cvt_f2h_kernel<<<cvtW_blocks, 256>>>(Wv, wh + (size_t)2 * H_ * H_);
    cvt_f2h_kernel<<<cvtW_blocks, 256>>>(Wo, wh + (size_t)3 * H_ * H_);
    biascat_kernel<<<H3_ / 256, 256>>>(bq, bk, bv, bc);

    // --- stage 2: fused QKV projection (N=6144) -> packed fp16 QKV ---
    dim3 qkv_grid(H3_ / 128, M_ / 128);            // (48, 32)
    gemm2_kernel<<<qkv_grid, 256, GEMM_SMEM>>>(ah, wh, bc, qkvh, nullptr, H3_);

    // --- stage 3: attention -> fp16 into g_Ah (stage-4 input) ---
    dim3 agrid(S_ / 128, B_ * NH_);                // (16, 32)
    attn_mma_kernel<<<agrid, 256, ATTN_SMEM>>>(qkvh, ah);

    // --- stage 4: output projection (fp32 out) ---
    dim3 ogrid(H_ / 128, M_ / 128);                // (16, 32)
    gemm2_kernel<<<ogrid, 256, GEMM_SMEM>>>(
        ah, wh + (size_t)3 * H_ * H_, bo, nullptr, out, H_);
}